// round 1
// baseline (speedup 1.0000x reference)
#include <cuda_runtime.h>
#include <cuda_fp16.h>

#define NPTS 6144
#define NUM_ITERS 10

// Scratch (static device globals — allocation-free per harness rules)
__device__ __half d_M[(size_t)NPTS * NPTS];   // 75.5 MB, fits in L2
__device__ float  d_v0[NPTS];
__device__ float  d_v1[NPTS];
__device__ float  d_ss[NUM_ITERS];

__device__ __forceinline__ float fsqrt_approx(float x) {
    float r;
    asm("sqrt.approx.f32 %0, %1;" : "=f"(r) : "f"(x));
    return r;
}

__device__ __forceinline__ unsigned pack_half2(float a, float b) {
    __half2 h = __floats2half2_rn(a, b);
    return *reinterpret_cast<unsigned*>(&h);
}

__global__ void k_init() {
    int i = blockIdx.x * blockDim.x + threadIdx.x;
    if (i < NPTS)      d_v0[i] = 1.0f;
    if (i < NUM_ITERS) d_ss[i] = 0.0f;
}

// Build M in fp16. Each thread computes an 8x8 tile (register-resident points).
// M[i][j] = max(0, 1 - 100*(a + b - 2*sqrt(a*b))), a=|p2_i-p2_j|^2, b=|p3_i-p3_j|^2
__global__ void __launch_bounds__(256) k_build(const float* __restrict__ p2,
                                               const float* __restrict__ p3) {
    const int tid = threadIdx.x;
    const int j0 = (blockIdx.x * 256 + tid) * 8;   // 8 cols
    const int r0 = blockIdx.y * 8;                 // 8 rows

    const float4* p2v = reinterpret_cast<const float4*>(p2);
    const float4* p3v = reinterpret_cast<const float4*>(p3);

    // column points (per-thread, coalesced)
    float cx[8], cy[8];
#pragma unroll
    for (int k = 0; k < 4; k++) {
        float4 a = __ldg(&p2v[j0 / 2 + k]);
        cx[2*k] = a.x; cy[2*k] = a.y; cx[2*k+1] = a.z; cy[2*k+1] = a.w;
    }
    float q3[24];
#pragma unroll
    for (int k = 0; k < 6; k++) {
        float4 a = __ldg(&p3v[(3 * j0) / 4 + k]);
        q3[4*k] = a.x; q3[4*k+1] = a.y; q3[4*k+2] = a.z; q3[4*k+3] = a.w;
    }
    // row points (uniform across block -> L1 broadcast)
    float rx[8], ry[8];
#pragma unroll
    for (int k = 0; k < 4; k++) {
        float4 a = __ldg(&p2v[r0 / 2 + k]);
        rx[2*k] = a.x; ry[2*k] = a.y; rx[2*k+1] = a.z; ry[2*k+1] = a.w;
    }
    float r3[24];
#pragma unroll
    for (int k = 0; k < 6; k++) {
        float4 a = __ldg(&p3v[(3 * r0) / 4 + k]);
        r3[4*k] = a.x; r3[4*k+1] = a.y; r3[4*k+2] = a.z; r3[4*k+3] = a.w;
    }

#pragma unroll
    for (int r = 0; r < 8; r++) {
        const float x2 = rx[r], y2 = ry[r];
        const float x3 = r3[3*r], y3 = r3[3*r+1], z3 = r3[3*r+2];
        float m[8];
#pragma unroll
        for (int c = 0; c < 8; c++) {
            float dx = x2 - cx[c];
            float dy = y2 - cy[c];
            float a  = fmaf(dy, dy, dx * dx);
            float d0 = x3 - q3[3*c];
            float d1 = y3 - q3[3*c+1];
            float d2 = z3 - q3[3*c+2];
            float b  = fmaf(d2, d2, fmaf(d1, d1, d0 * d0));
            float s  = fsqrt_approx(a * b);           // sqrt(a)*sqrt(b)
            float cr = a + b - 2.0f * s;              // (sqrt(a)-sqrt(b))^2
            m[c] = fmaxf(fmaf(-100.0f, cr, 1.0f), 0.0f);
        }
        uint4 o;
        o.x = pack_half2(m[0], m[1]);
        o.y = pack_half2(m[2], m[3]);
        o.z = pack_half2(m[4], m[5]);
        o.w = pack_half2(m[6], m[7]);
        *reinterpret_cast<uint4*>(&d_M[(size_t)(r0 + r) * NPTS + j0]) = o;
    }
}

// One power-iteration step: u_k = M * (u_{k-1} / (||u_{k-1}||+1e-6)).
// Scale by the previous norm applied at the output; accumulate ||u_k||^2.
// Warp-per-row, 8 rows/block, x staged deinterleaved in smem (conflict-free LDS.128).
__global__ void __launch_bounds__(256) k_gemv(int k) {
    const float* __restrict__ x = (k & 1) ? d_v1 : d_v0;
    float* __restrict__       y = (k & 1) ? d_v0 : d_v1;

    __shared__ float4 sA[NPTS / 8];   // x4[2i]
    __shared__ float4 sB[NPTS / 8];   // x4[2i+1]
    __shared__ float  wsum[8];

    const int tid = threadIdx.x;
    const float4* xv = reinterpret_cast<const float4*>(x);
#pragma unroll
    for (int t = 0; t < 3; t++) {
        int i = tid + 256 * t;
        sA[i] = xv[2 * i];
        sB[i] = xv[2 * i + 1];
    }
    __syncthreads();

    float scale = 1.0f;
    if (k > 0) scale = 1.0f / (sqrtf(d_ss[k - 1]) + 1e-6f);

    const int warp = tid >> 5, lane = tid & 31;
    const int row = blockIdx.x * 8 + warp;
    const uint4* mrow = reinterpret_cast<const uint4*>(&d_M[(size_t)row * NPTS]);

    float acc0 = 0.0f, acc1 = 0.0f;
#pragma unroll
    for (int it = 0; it < 24; it++) {
        const int idx = it * 32 + lane;
        uint4 mv = __ldg(&mrow[idx]);
        float4 xa = sA[idx];
        float4 xb = sB[idx];
        __half2 h;
        float2 f;
        *reinterpret_cast<unsigned*>(&h) = mv.x; f = __half22float2(h);
        acc0 = fmaf(f.x, xa.x, acc0); acc0 = fmaf(f.y, xa.y, acc0);
        *reinterpret_cast<unsigned*>(&h) = mv.y; f = __half22float2(h);
        acc1 = fmaf(f.x, xa.z, acc1); acc1 = fmaf(f.y, xa.w, acc1);
        *reinterpret_cast<unsigned*>(&h) = mv.z; f = __half22float2(h);
        acc0 = fmaf(f.x, xb.x, acc0); acc0 = fmaf(f.y, xb.y, acc0);
        *reinterpret_cast<unsigned*>(&h) = mv.w; f = __half22float2(h);
        acc1 = fmaf(f.x, xb.z, acc1); acc1 = fmaf(f.y, xb.w, acc1);
    }
    float acc = acc0 + acc1;
#pragma unroll
    for (int o = 16; o; o >>= 1) acc += __shfl_xor_sync(0xffffffffu, acc, o);

    if (lane == 0) {
        float v = acc * scale;
        y[row] = v;
        wsum[warp] = v * v;
    }
    __syncthreads();
    if (tid == 0) {
        float s = 0.0f;
#pragma unroll
        for (int w = 0; w < 8; w++) s += wsum[w];
        atomicAdd(&d_ss[k], s);
    }
}

// Final normalization into d_out (last raw result lives in d_v0 after 10 iters).
__global__ void k_final(float* __restrict__ out) {
    int i = blockIdx.x * blockDim.x + threadIdx.x;
    float inv = 1.0f / (sqrtf(d_ss[NUM_ITERS - 1]) + 1e-6f);
    if (i < NPTS) out[i] = d_v0[i] * inv;
}

extern "C" void kernel_launch(void* const* d_in, const int* in_sizes, int n_in,
                              void* d_out, int out_size) {
    const float* p2 = (const float*)d_in[0];  // ipts2d (N,2) fp32
    const float* p3 = (const float*)d_in[1];  // ipts3d (N,3) fp32

    k_init<<<24, 256>>>();
    dim3 bgrid(3, NPTS / 8);                  // 8x8 tile per thread
    k_build<<<bgrid, 256>>>(p2, p3);
    for (int k = 0; k < NUM_ITERS; k++)
        k_gemv<<<NPTS / 8, 256>>>(k);
    k_final<<<24, 256>>>((float*)d_out);
}

// round 2
// speedup vs baseline: 1.1741x; 1.1741x over previous
#include <cuda_runtime.h>

#define NPTS 6144
#define NITERS 10

// Scratch (static device globals — allocation-free per harness rules)
__device__ unsigned char d_M[(size_t)NPTS * NPTS];   // 37.7 MB u8 matrix, L2-resident
__device__ float d_v0[NPTS];
__device__ float d_v1[NPTS];

__device__ __forceinline__ float fsqrt_approx(float x) {
    float r;
    asm("sqrt.approx.f32 %0, %1;" : "=f"(r) : "f"(x));
    return r;
}

__global__ void k_init() {
    int i = blockIdx.x * blockDim.x + threadIdx.x;
    if (i < NPTS) d_v0[i] = 1.0f;
}

// Build M in u8 fixed-point: q = round(255 * max(0, 1 - 100*cross^2)),
// cross^2 = a + b - 2*sqrt(a*b), a=|p2_i-p2_j|^2, b=|p3_i-p3_j|^2.
// Each thread computes an 8x8 tile (register-resident points).
__global__ void __launch_bounds__(256) k_build(const float* __restrict__ p2,
                                               const float* __restrict__ p3) {
    const int tid = threadIdx.x;
    const int j0 = (blockIdx.x * 256 + tid) * 8;   // 8 cols
    const int r0 = blockIdx.y * 8;                 // 8 rows

    const float4* p2v = reinterpret_cast<const float4*>(p2);
    const float4* p3v = reinterpret_cast<const float4*>(p3);

    float cx[8], cy[8];
#pragma unroll
    for (int k = 0; k < 4; k++) {
        float4 a = __ldg(&p2v[j0 / 2 + k]);
        cx[2*k] = a.x; cy[2*k] = a.y; cx[2*k+1] = a.z; cy[2*k+1] = a.w;
    }
    float q3[24];
#pragma unroll
    for (int k = 0; k < 6; k++) {
        float4 a = __ldg(&p3v[(3 * j0) / 4 + k]);
        q3[4*k] = a.x; q3[4*k+1] = a.y; q3[4*k+2] = a.z; q3[4*k+3] = a.w;
    }
    float rx[8], ry[8];
#pragma unroll
    for (int k = 0; k < 4; k++) {
        float4 a = __ldg(&p2v[r0 / 2 + k]);
        rx[2*k] = a.x; ry[2*k] = a.y; rx[2*k+1] = a.z; ry[2*k+1] = a.w;
    }
    float r3[24];
#pragma unroll
    for (int k = 0; k < 6; k++) {
        float4 a = __ldg(&p3v[(3 * r0) / 4 + k]);
        r3[4*k] = a.x; r3[4*k+1] = a.y; r3[4*k+2] = a.z; r3[4*k+3] = a.w;
    }

#pragma unroll
    for (int r = 0; r < 8; r++) {
        const float x2 = rx[r], y2 = ry[r];
        const float x3 = r3[3*r], y3 = r3[3*r+1], z3 = r3[3*r+2];
        unsigned q[8];
#pragma unroll
        for (int c = 0; c < 8; c++) {
            float dx = x2 - cx[c];
            float dy = y2 - cy[c];
            float a  = fmaf(dy, dy, dx * dx);
            float d0 = x3 - q3[3*c];
            float d1 = y3 - q3[3*c+1];
            float d2 = z3 - q3[3*c+2];
            float b  = fmaf(d2, d2, fmaf(d1, d1, d0 * d0));
            float s  = fsqrt_approx(a * b);              // sqrt(a)*sqrt(b)
            float cr = a + b - 2.0f * s;                 // (sqrt(a)-sqrt(b))^2
            float m  = fmaxf(fmaf(-25500.0f, cr, 255.0f), 0.0f);  // 255*clip(1-100cr)
            q[c] = __float2uint_rn(m);
        }
        unsigned w0 = q[0] | (q[1] << 8) | (q[2] << 16) | (q[3] << 24);
        unsigned w1 = q[4] | (q[5] << 8) | (q[6] << 16) | (q[7] << 24);
        *reinterpret_cast<uint2*>(&d_M[(size_t)(r0 + r) * NPTS + j0]) =
            make_uint2(w0, w1);
    }
}

// Unpack 4 u8 cols and FMA against float4 x.
__device__ __forceinline__ float dotq(float acc, unsigned w, float4 x) {
    acc = fmaf((float)(w & 255u),         x.x, acc);
    acc = fmaf((float)((w >> 8) & 255u),  x.y, acc);
    acc = fmaf((float)((w >> 16) & 255u), x.z, acc);
    acc = fmaf((float)(w >> 24),          x.w, acc);
    return acc;
}

// One power-iteration step: y = M * (x / (||x||+1e-6)) with the 1/255 dequant
// folded into the output scale. ||x||^2 computed per-CTA from staged values
// (identical deterministic reduction in every CTA). 4 rows/warp reuse each
// staged x chunk; smem padded (+1 float4 per 8) for conflict-free LDS.128.
__global__ void __launch_bounds__(128) k_gemv(int k) {
    const float* __restrict__ x = (k & 1) ? d_v1 : d_v0;
    float* __restrict__       y = (k & 1) ? d_v0 : d_v1;

    __shared__ float4 sx[1536 + 192];   // padded: phys = f + (f>>3)
    __shared__ float red[4];

    const int tid = threadIdx.x;
    const float4* xv = reinterpret_cast<const float4*>(x);

    float ss = 0.0f;
#pragma unroll
    for (int t = 0; t < 12; t++) {
        int f = tid + 128 * t;
        float4 v = xv[f];
        sx[f + (f >> 3)] = v;
        ss = fmaf(v.x, v.x, fmaf(v.y, v.y, fmaf(v.z, v.z, fmaf(v.w, v.w, ss))));
    }
#pragma unroll
    for (int o = 16; o; o >>= 1) ss += __shfl_xor_sync(0xffffffffu, ss, o);
    if ((tid & 31) == 0) red[tid >> 5] = ss;
    __syncthreads();
    ss = red[0] + red[1] + red[2] + red[3];

    const float scale = (k == 0) ? (1.0f / 255.0f)
                                 : (1.0f / (255.0f * (sqrtf(ss) + 1e-6f)));

    const int warp = tid >> 5, lane = tid & 31;
    const int r0 = blockIdx.x * 16 + warp * 4;
    const uint4* M4 = reinterpret_cast<const uint4*>(d_M);
    const size_t rb = (size_t)r0 * (NPTS / 16);   // uint4 index of row r0

    float a0 = 0.0f, a1 = 0.0f, a2 = 0.0f, a3 = 0.0f;
#pragma unroll
    for (int it = 0; it < 12; it++) {
        const int c = it * 32 + lane;     // 16-col chunk id
        const int f0 = 4 * c;
        float4 x0 = sx[(f0    ) + ((f0    ) >> 3)];
        float4 x1 = sx[(f0 + 1) + ((f0 + 1) >> 3)];
        float4 x2 = sx[(f0 + 2) + ((f0 + 2) >> 3)];
        float4 x3 = sx[(f0 + 3) + ((f0 + 3) >> 3)];
        uint4 m0 = __ldg(&M4[rb              + c]);
        uint4 m1 = __ldg(&M4[rb +  1 * 384   + c]);
        uint4 m2 = __ldg(&M4[rb +  2 * 384   + c]);
        uint4 m3 = __ldg(&M4[rb +  3 * 384   + c]);
        a0 = dotq(dotq(dotq(dotq(a0, m0.x, x0), m0.y, x1), m0.z, x2), m0.w, x3);
        a1 = dotq(dotq(dotq(dotq(a1, m1.x, x0), m1.y, x1), m1.z, x2), m1.w, x3);
        a2 = dotq(dotq(dotq(dotq(a2, m2.x, x0), m2.y, x1), m2.z, x2), m2.w, x3);
        a3 = dotq(dotq(dotq(dotq(a3, m3.x, x0), m3.y, x1), m3.z, x2), m3.w, x3);
    }
#pragma unroll
    for (int o = 16; o; o >>= 1) {
        a0 += __shfl_xor_sync(0xffffffffu, a0, o);
        a1 += __shfl_xor_sync(0xffffffffu, a1, o);
        a2 += __shfl_xor_sync(0xffffffffu, a2, o);
        a3 += __shfl_xor_sync(0xffffffffu, a3, o);
    }
    if (lane == 0) {
        y[r0    ] = a0 * scale;
        y[r0 + 1] = a1 * scale;
        y[r0 + 2] = a2 * scale;
        y[r0 + 3] = a3 * scale;
    }
}

// Final normalization into d_out. Each block redundantly computes the norm
// (deterministic), then writes its slice.
__global__ void __launch_bounds__(256) k_final(float* __restrict__ out) {
    __shared__ float red[8];
    const int tid = threadIdx.x;
    float ss = 0.0f;
#pragma unroll
    for (int t = 0; t < 24; t++) {
        float v = d_v0[tid + 256 * t];
        ss = fmaf(v, v, ss);
    }
#pragma unroll
    for (int o = 16; o; o >>= 1) ss += __shfl_xor_sync(0xffffffffu, ss, o);
    if ((tid & 31) == 0) red[tid >> 5] = ss;
    __syncthreads();
    ss = 0.0f;
#pragma unroll
    for (int w = 0; w < 8; w++) ss += red[w];
    const float inv = 1.0f / (sqrtf(ss) + 1e-6f);
    const int i = blockIdx.x * 256 + tid;
    out[i] = d_v0[i] * inv;
}

extern "C" void kernel_launch(void* const* d_in, const int* in_sizes, int n_in,
                              void* d_out, int out_size) {
    const float* p2 = (const float*)d_in[0];  // ipts2d (N,2) fp32
    const float* p3 = (const float*)d_in[1];  // ipts3d (N,3) fp32

    k_init<<<24, 256>>>();
    dim3 bgrid(3, NPTS / 8);                  // 8x8 tile per thread
    k_build<<<bgrid, 256>>>(p2, p3);
    for (int k = 0; k < NITERS; k++)
        k_gemv<<<NPTS / 16, 128>>>(k);        // 384 blocks, 16 rows each
    k_final<<<NPTS / 256, 256>>>((float*)d_out);
}

// round 3
// speedup vs baseline: 1.5204x; 1.2950x over previous
#include <cuda_runtime.h>

#define NPTS 6144
#define NITERS 10

// Scratch (static device globals — allocation-free per harness rules)
__device__ unsigned char d_M[(size_t)NPTS * NPTS];   // 37.7 MB u8 matrix, L2-resident
__device__ float d_v0[NPTS];
__device__ float d_v1[NPTS];

__device__ __forceinline__ float fsqrt_approx(float x) {
    float r;
    asm("sqrt.approx.f32 %0, %1;" : "=f"(r) : "f"(x));
    return r;
}

__global__ void k_init() {
    int i = blockIdx.x * blockDim.x + threadIdx.x;
    if (i < NPTS) d_v0[i] = 1.0f;
}

// Build M in u8 fixed-point: q = round(255 * max(0, 1 - 100*cross^2)),
// cross^2 = a + b - 2*sqrt(a*b), a=|p2_i-p2_j|^2, b=|p3_i-p3_j|^2.
// Rounding via 2^23 magic add fused into the final FMA (no F2I).
__global__ void __launch_bounds__(256) k_build(const float* __restrict__ p2,
                                               const float* __restrict__ p3) {
    const int tid = threadIdx.x;
    const int j0 = (blockIdx.x * 256 + tid) * 8;   // 8 cols
    const int r0 = blockIdx.y * 8;                 // 8 rows

    const float4* p2v = reinterpret_cast<const float4*>(p2);
    const float4* p3v = reinterpret_cast<const float4*>(p3);

    float cx[8], cy[8];
#pragma unroll
    for (int k = 0; k < 4; k++) {
        float4 a = __ldg(&p2v[j0 / 2 + k]);
        cx[2*k] = a.x; cy[2*k] = a.y; cx[2*k+1] = a.z; cy[2*k+1] = a.w;
    }
    float q3[24];
#pragma unroll
    for (int k = 0; k < 6; k++) {
        float4 a = __ldg(&p3v[(3 * j0) / 4 + k]);
        q3[4*k] = a.x; q3[4*k+1] = a.y; q3[4*k+2] = a.z; q3[4*k+3] = a.w;
    }
    float rx[8], ry[8];
#pragma unroll
    for (int k = 0; k < 4; k++) {
        float4 a = __ldg(&p2v[r0 / 2 + k]);
        rx[2*k] = a.x; ry[2*k] = a.y; rx[2*k+1] = a.z; ry[2*k+1] = a.w;
    }
    float r3[24];
#pragma unroll
    for (int k = 0; k < 6; k++) {
        float4 a = __ldg(&p3v[(3 * r0) / 4 + k]);
        r3[4*k] = a.x; r3[4*k+1] = a.y; r3[4*k+2] = a.z; r3[4*k+3] = a.w;
    }

#pragma unroll
    for (int r = 0; r < 8; r++) {
        const float x2 = rx[r], y2 = ry[r];
        const float x3 = r3[3*r], y3 = r3[3*r+1], z3 = r3[3*r+2];
        unsigned u[8];
#pragma unroll
        for (int c = 0; c < 8; c++) {
            float dx = x2 - cx[c];
            float dy = y2 - cy[c];
            float a  = fmaf(dy, dy, dx * dx);
            float d0 = x3 - q3[3*c];
            float d1 = y3 - q3[3*c+1];
            float d2 = z3 - q3[3*c+2];
            float b  = fmaf(d2, d2, fmaf(d1, d1, d0 * d0));
            float s  = fsqrt_approx(a * b);              // sqrt(a)*sqrt(b)
            float cr = fmaf(-2.0f, s, a + b);            // (sqrt(a)-sqrt(b))^2
            // t = 8388608 + round(clamp(255 - 25500*cr, 0, 255)); byte = mantissa low 8
            float t  = fminf(fmaxf(fmaf(-25500.0f, cr, 8388863.0f), 8388608.0f),
                             8388863.0f);
            u[c] = __float_as_uint(t);
        }
        unsigned w0 = __byte_perm(__byte_perm(u[0], u[1], 0x0040),
                                  __byte_perm(u[2], u[3], 0x0040), 0x5410);
        unsigned w1 = __byte_perm(__byte_perm(u[4], u[5], 0x0040),
                                  __byte_perm(u[6], u[7], 0x0040), 0x5410);
        *reinterpret_cast<uint2*>(&d_M[(size_t)(r0 + r) * NPTS + j0]) =
            make_uint2(w0, w1);
    }
}

// One power-iteration step via integer dp4a:
//   x_hat = x / (||x||+1e-6)   (k=0: x_hat = x = ones, no normalization)
//   xq    = round(x_hat * 65535) stored as lo/hi u8 byte planes in smem
//   y_i   = (Σ_j M_ij*xq_lo_j + 256*Σ_j M_ij*xq_hi_j) / (255*65535)
// All accumulation exact in u32. 2 rows/warp, 8 rows/block, grid 768.
__global__ void __launch_bounds__(128) k_gemv(int k) {
    const float* __restrict__ x = (k & 1) ? d_v1 : d_v0;
    float* __restrict__       y = (k & 1) ? d_v0 : d_v1;

    __shared__ unsigned sxlo[NPTS / 4];   // 1536 words, lo bytes of xq
    __shared__ unsigned sxhi[NPTS / 4];   // hi bytes of xq
    __shared__ float red[4];

    const int tid = threadIdx.x;
    const float4* xv = reinterpret_cast<const float4*>(x);

    float4 v[12];
    float ss = 0.0f;
#pragma unroll
    for (int t = 0; t < 12; t++) {
        v[t] = xv[tid + 128 * t];
        ss = fmaf(v[t].x, v[t].x, fmaf(v[t].y, v[t].y,
             fmaf(v[t].z, v[t].z, fmaf(v[t].w, v[t].w, ss))));
    }
#pragma unroll
    for (int o = 16; o; o >>= 1) ss += __shfl_xor_sync(0xffffffffu, ss, o);
    if ((tid & 31) == 0) red[tid >> 5] = ss;
    __syncthreads();
    ss = red[0] + red[1] + red[2] + red[3];

    const float inv = (k == 0) ? 1.0f : (1.0f / (sqrtf(ss) + 1e-6f));
    const float qs  = 65535.0f * inv;

#pragma unroll
    for (int t = 0; t < 12; t++) {
        unsigned q0 = __float2uint_rn(v[t].x * qs);
        unsigned q1 = __float2uint_rn(v[t].y * qs);
        unsigned q2 = __float2uint_rn(v[t].z * qs);
        unsigned q3 = __float2uint_rn(v[t].w * qs);
        const int f = tid + 128 * t;
        sxlo[f] = (q0 & 255u) | ((q1 & 255u) << 8) |
                  ((q2 & 255u) << 16) | ((q3 & 255u) << 24);
        sxhi[f] = (q0 >> 8) | ((q1 >> 8) << 8) |
                  ((q2 >> 8) << 16) | ((q3 >> 8) << 24);
    }
    __syncthreads();

    const int warp = tid >> 5, lane = tid & 31;
    const int r0 = blockIdx.x * 8 + warp * 2;
    const uint4* M4  = reinterpret_cast<const uint4*>(d_M);
    const uint4* sl4 = reinterpret_cast<const uint4*>(sxlo);
    const uint4* sh4 = reinterpret_cast<const uint4*>(sxhi);
    const size_t rb = (size_t)r0 * (NPTS / 16);

    unsigned lo0 = 0, hi0 = 0, lo1 = 0, hi1 = 0;
#pragma unroll
    for (int it = 0; it < 12; it++) {
        const int c = it * 32 + lane;     // 16-column chunk id
        uint4 xl = sl4[c];
        uint4 xh = sh4[c];
        uint4 m0 = __ldg(&M4[rb + c]);
        uint4 m1 = __ldg(&M4[rb + (NPTS / 16) + c]);
        lo0 = __dp4a(m0.x, xl.x, lo0); hi0 = __dp4a(m0.x, xh.x, hi0);
        lo0 = __dp4a(m0.y, xl.y, lo0); hi0 = __dp4a(m0.y, xh.y, hi0);
        lo0 = __dp4a(m0.z, xl.z, lo0); hi0 = __dp4a(m0.z, xh.z, hi0);
        lo0 = __dp4a(m0.w, xl.w, lo0); hi0 = __dp4a(m0.w, xh.w, hi0);
        lo1 = __dp4a(m1.x, xl.x, lo1); hi1 = __dp4a(m1.x, xh.x, hi1);
        lo1 = __dp4a(m1.y, xl.y, lo1); hi1 = __dp4a(m1.y, xh.y, hi1);
        lo1 = __dp4a(m1.z, xl.z, lo1); hi1 = __dp4a(m1.z, xh.z, hi1);
        lo1 = __dp4a(m1.w, xl.w, lo1); hi1 = __dp4a(m1.w, xh.w, hi1);
    }
#pragma unroll
    for (int o = 16; o; o >>= 1) {
        lo0 += __shfl_xor_sync(0xffffffffu, lo0, o);
        hi0 += __shfl_xor_sync(0xffffffffu, hi0, o);
        lo1 += __shfl_xor_sync(0xffffffffu, lo1, o);
        hi1 += __shfl_xor_sync(0xffffffffu, hi1, o);
    }
    if (lane == 0) {
        const float outsc = 1.0f / (255.0f * 65535.0f);
        y[r0    ] = ((float)lo0 + 256.0f * (float)hi0) * outsc;
        y[r0 + 1] = ((float)lo1 + 256.0f * (float)hi1) * outsc;
    }
}

// Final normalization into d_out (last raw result in d_v0 after 10 iters).
__global__ void __launch_bounds__(256) k_final(float* __restrict__ out) {
    __shared__ float red[8];
    const int tid = threadIdx.x;
    float ss = 0.0f;
#pragma unroll
    for (int t = 0; t < 24; t++) {
        float v = d_v0[tid + 256 * t];
        ss = fmaf(v, v, ss);
    }
#pragma unroll
    for (int o = 16; o; o >>= 1) ss += __shfl_xor_sync(0xffffffffu, ss, o);
    if ((tid & 31) == 0) red[tid >> 5] = ss;
    __syncthreads();
    ss = 0.0f;
#pragma unroll
    for (int w = 0; w < 8; w++) ss += red[w];
    const float inv = 1.0f / (sqrtf(ss) + 1e-6f);
    const int i = blockIdx.x * 256 + tid;
    out[i] = d_v0[i] * inv;
}

extern "C" void kernel_launch(void* const* d_in, const int* in_sizes, int n_in,
                              void* d_out, int out_size) {
    const float* p2 = (const float*)d_in[0];  // ipts2d (N,2) fp32
    const float* p3 = (const float*)d_in[1];  // ipts3d (N,3) fp32

    k_init<<<24, 256>>>();
    dim3 bgrid(3, NPTS / 8);                  // 8x8 tile per thread
    k_build<<<bgrid, 256>>>(p2, p3);
    for (int k = 0; k < NITERS; k++)
        k_gemv<<<NPTS / 8, 128>>>(k);         // 768 blocks, 8 rows each
    k_final<<<NPTS / 256, 256>>>((float*)d_out);
}